// round 15
// baseline (speedup 1.0000x reference)
#include <cuda_runtime.h>
#include <math.h>
#include <stdint.h>

#define B_   8192
#define IN_  4096
#define H_   1024
#define P_   2048
#define NW_  3
#define NC_  1000
#define H2_  2048

// ---------------- scratch ----------------
__device__ float d_xT  [(size_t)IN_ * B_];
__device__ float d_h   [(size_t)B_ * P_];
__device__ float d_hT  [(size_t)P_ * B_];
__device__ float d_out2[(size_t)B_ * NW_ * H2_];
__device__ float d_supr[(size_t)B_ * H_];
__device__ float d_supi[(size_t)B_ * H_];
__device__ float d_magA[(size_t)B_ * H_];
__device__ float d_magB[(size_t)B_ * H_];
__device__ float d_magAT[(size_t)H_ * B_];
__device__ float d_magBT[(size_t)H_ * B_];
__device__ float d_t1  [(size_t)B_ * H_];
__device__ float d_t1T [(size_t)H_ * B_];
__device__ float d_W2p [(size_t)H_ * 1024];
__device__ float d_su[NW_ * P_];
__device__ float d_sv[NW_ * P_];
__device__ float d_st[NW_ * P_];
__device__ float d_snp[NW_ * 8 * H2_];
__device__ float d_sigma_inv[NW_];

// ---------------- helpers ----------------
__device__ __forceinline__ uint32_t smem_u32(const void* p) {
    uint32_t a;
    asm("{ .reg .u64 t; cvta.to.shared.u64 t, %1; cvt.u32.u64 %0, t; }" : "=r"(a) : "l"(p));
    return a;
}
__device__ __forceinline__ void cp16(uint32_t dst, const void* src) {
    asm volatile("cp.async.cg.shared.global [%0], [%1], 16;\n" :: "r"(dst), "l"(src));
}
#define CP_COMMIT() asm volatile("cp.async.commit_group;\n")
#define CP_WAIT1()  asm volatile("cp.async.wait_group 1;\n" ::: "memory")
#define CP_WAIT0()  asm volatile("cp.async.wait_group 0;\n" ::: "memory")

__device__ __forceinline__ void ffma2(unsigned long long& acc, unsigned long long a,
                                      unsigned long long b) {
    asm("fma.rn.f32x2 %0, %1, %2, %0;" : "+l"(acc) : "l"(a), "l"(b));
}
__device__ __forceinline__ unsigned long long dup2(float v) {
    unsigned long long r;
    asm("mov.b64 %0, {%1, %1};" : "=l"(r) : "f"(v));
    return r;
}
__device__ __forceinline__ void upk2(unsigned long long v, float& lo, float& hi) {
    asm("mov.b64 {%0, %1}, %2;" : "=f"(lo), "=f"(hi) : "l"(v));
}
__device__ __forceinline__ float gelu_f(float x) {
    return 0.5f * x * (1.f + erff(x * 0.70710678118654752440f));
}
__device__ __forceinline__ float blockReduceSum(float v) {
    __shared__ float sh[33];
    int lane = threadIdx.x & 31, wid = threadIdx.x >> 5;
    #pragma unroll
    for (int o = 16; o; o >>= 1) v += __shfl_xor_sync(0xffffffffu, v, o);
    __syncthreads();
    if (lane == 0) sh[wid] = v;
    __syncthreads();
    if (wid == 0) {
        int nw = (blockDim.x + 31) >> 5;
        float r = (lane < nw) ? sh[lane] : 0.f;
        #pragma unroll
        for (int o = 16; o; o >>= 1) r += __shfl_xor_sync(0xffffffffu, r, o);
        if (lane == 0) sh[32] = r;
    }
    __syncthreads();
    return sh[32];
}

// ---------------- persistent SGEMM, cross-tile continuous cp.async pipeline ----------------
// C[M,N] = A[M,K] @ B[K,N]; A given transposed (AT [K][M], ld=ldA); B row-major [K][N].
// Tile 128x128x32, 3 stages; next tile's first stages prefetched under current epilogue.
// Per-element FMA order k-ascending, identical to R12 -> bit-identical outputs.
// EPI: 0 +bias store ; 1 *sigma_inv[z]+bias ; 2 sigmoid gate update ; 4 +bias col<Nreal
#define SG_SMEM 98304
#define NCTA 296

template<int EPI>
__global__ void __launch_bounds__(256, 2)
sgemm(const float* __restrict__ AT, int ldA,
      const float* __restrict__ Bm, int ldB, long long bZ,
      const float* __restrict__ bias, long long biasZ,
      float* __restrict__ C, int ldc, long long cZ,
      int K,
      float* __restrict__ supr, float* __restrict__ supi,
      float* __restrict__ magRM, int Nreal,
      int gx, int gy, int ntiles)
{
    extern __shared__ float smf[];
    float* As = smf;                 // [3][32][128]
    float* Bs = smf + 3 * 32 * 128;  // [3][32][128]
    const int tid = threadIdx.x;
    const int tr = (tid >> 4) * 8;
    const int tc = (tid & 15) * 4;
    const uint32_t sA = smem_u32(As);
    const uint32_t sB = smem_u32(Bs);
    const int nit = K / 32;          // >= 2 for all our GEMMs

    int t = blockIdx.x;
    if (t >= ntiles) return;

    auto load_stage = [&](int st, int k0, int br, int bc, const float* Bp) {
        #pragma unroll
        for (int j = 0; j < 4; j++) {
            int c = tid + j * 256;
            int kr = c >> 5, sg = c & 31;
            cp16(sA + st * 16384 + kr * 512 + sg * 16,
                 AT + (size_t)(k0 + kr) * ldA + br + sg * 4);
            cp16(sB + st * 16384 + kr * 512 + sg * 16,
                 Bp + (size_t)(k0 + kr) * ldB + bc + sg * 4);
        }
    };

    int brow, bcol;
    const float* Bz;
    {
        int tx = t % gx, rem = t / gx;
        brow = (rem % gy) * 128; bcol = tx * 128;
        Bz = Bm + (size_t)(rem / gy) * bZ;
    }

    load_stage(0, 0, brow, bcol, Bz);  CP_COMMIT();
    load_stage(1, 32, brow, bcol, Bz); CP_COMMIT();
    int stg = 0;

    while (true) {
        const int tn = t + gridDim.x;
        int brow2 = 0, bcol2 = 0;
        const float* Bz2 = Bm;
        const bool hasNext = (tn < ntiles);
        if (hasNext) {
            int tx = tn % gx, rem = tn / gx;
            brow2 = (rem % gy) * 128; bcol2 = tx * 128;
            Bz2 = Bm + (size_t)(rem / gy) * bZ;
        }

        unsigned long long acc[4][8];
        #pragma unroll
        for (int i = 0; i < 4; i++)
            #pragma unroll
            for (int j = 0; j < 8; j++) acc[i][j] = 0ull;

        for (int it = 0; it < nit; ++it) {
            CP_WAIT1();
            __syncthreads();
            int s2 = stg + 2; if (s2 >= 3) s2 -= 3;
            int ps = it + 2;
            if (ps < nit)       load_stage(s2, ps * 32, brow, bcol, Bz);
            else if (hasNext)   load_stage(s2, (ps - nit) * 32, brow2, bcol2, Bz2);
            CP_COMMIT();

            const float* Ab = As + stg * 4096;
            const float* Bb = Bs + stg * 4096;
            #pragma unroll
            for (int kk = 0; kk < 32; kk++) {
                ulonglong2 av0 = *(const ulonglong2*)(Ab + kk * 128 + tr);
                ulonglong2 av1 = *(const ulonglong2*)(Ab + kk * 128 + tr + 4);
                float4 b0 = *(const float4*)(Bb + kk * 128 + tc);
                float4 b1 = *(const float4*)(Bb + kk * 128 + tc + 64);
                unsigned long long bd[8];
                bd[0] = dup2(b0.x); bd[1] = dup2(b0.y); bd[2] = dup2(b0.z); bd[3] = dup2(b0.w);
                bd[4] = dup2(b1.x); bd[5] = dup2(b1.y); bd[6] = dup2(b1.z); bd[7] = dup2(b1.w);
                unsigned long long ap[4] = { av0.x, av0.y, av1.x, av1.y };
                #pragma unroll
                for (int i = 0; i < 4; i++)
                    #pragma unroll
                    for (int j = 0; j < 8; j++)
                        ffma2(acc[i][j], ap[i], bd[j]);
            }
            stg = stg + 1; if (stg >= 3) stg -= 3;
        }

        // epilogue (overlaps with next tile's in-flight stage loads)
        {
            const int z = t / (gx * gy);
            const float* biasz = bias + (size_t)z * biasZ;
            const float scale = (EPI == 1) ? d_sigma_inv[z] : 1.f;
            float* Cz = C + (size_t)z * cZ;

            #pragma unroll
            for (int i = 0; i < 4; i++) {
                float vlo[8], vhi[8];
                #pragma unroll
                for (int j = 0; j < 8; j++) upk2(acc[i][j], vlo[j], vhi[j]);
                #pragma unroll
                for (int half = 0; half < 2; half++) {
                    int row = brow + tr + 2 * i + half;
                    const float* vv = half ? vhi : vlo;
                    #pragma unroll
                    for (int g = 0; g < 2; g++) {
                        int col = bcol + tc + g * 64;
                        if (EPI != 2) {
                            if (EPI == 4 && col >= Nreal) continue;
                            float4 o;
                            o.x = vv[g*4+0] * scale + biasz[col + 0];
                            o.y = vv[g*4+1] * scale + biasz[col + 1];
                            o.z = vv[g*4+2] * scale + biasz[col + 2];
                            o.w = vv[g*4+3] * scale + biasz[col + 3];
                            *(float4*)(Cz + (size_t)row * ldc + col) = o;
                        } else {
                            #pragma unroll
                            for (int q = 0; q < 4; q++) {
                                int cc = col + q;
                                float v = vv[g*4+q] + biasz[cc];
                                float gt = 1.f / (1.f + expf(-v)) + 0.1f;
                                size_t idx = (size_t)row * ldc + cc;
                                float rr = supr[idx] * gt, ii = supi[idx] * gt;
                                supr[idx] = rr; supi[idx] = ii;
                                magRM[idx] = sqrtf(rr * rr + ii * ii + 1e-8f);
                            }
                        }
                    }
                }
            }
        }

        if (!hasNext) break;
        t = tn; brow = brow2; bcol = bcol2; Bz = Bz2;
    }
    CP_WAIT0();   // drain residual (empty) groups before exit
}

// ---------------- preprocessing ----------------
__global__ void __launch_bounds__(256)
transpose_k(const float* __restrict__ src, float* __restrict__ dst, int R, int C)
{
    __shared__ float t[32][33];
    int r0 = blockIdx.y * 32, c0 = blockIdx.x * 32;
    int tx = threadIdx.x & 31, ty = threadIdx.x >> 5;
    #pragma unroll
    for (int i = 0; i < 4; i++)
        t[ty + i * 8][tx] = src[(size_t)(r0 + ty + i * 8) * C + c0 + tx];
    __syncthreads();
    #pragma unroll
    for (int i = 0; i < 4; i++)
        dst[(size_t)(c0 + ty + i * 8) * R + r0 + tx] = t[tx][ty + i * 8];
}

__global__ void __launch_bounds__(256)
padW2_k(const float* __restrict__ W2, float* __restrict__ W2p)
{
    int i = blockIdx.x * 256 + threadIdx.x;
    int k = i >> 10, n = i & 1023;
    W2p[i] = (n < NC_) ? W2[(size_t)k * NC_ + n] : 0.f;
}

// LN + gelu, in place (row-major)
__global__ void __launch_bounds__(256)
ln_gelu_k(float* __restrict__ h, const float* __restrict__ g, const float* __restrict__ beta)
{
    const int b = blockIdx.x, tid = threadIdx.x;
    float* row = h + (size_t)b * P_;
    float x[8];
    float sm = 0.f;
    #pragma unroll
    for (int t = 0; t < 8; t++) { x[t] = row[tid + t * 256]; sm += x[t]; }
    float mean = blockReduceSum(sm) * (1.f / (float)P_);
    float vs = 0.f;
    #pragma unroll
    for (int t = 0; t < 8; t++) { float d = x[t] - mean; vs += d * d; }
    float var = blockReduceSum(vs) * (1.f / (float)P_);
    float inv = rsqrtf(var + 1e-5f);
    #pragma unroll
    for (int t = 0; t < 8; t++) {
        int j = tid + t * 256;
        float y = (x[t] - mean) * inv * g[j] + beta[j];
        row[j] = gelu_f(y);
    }
}

// ---------------- spectral normalization ----------------
__global__ void sn_init_k(float* __restrict__ u) {
    int z = blockIdx.y;
    int j = blockIdx.x * 256 + threadIdx.x;
    u[z * P_ + j] = 1.f / sqrtf((float)P_);
}
__global__ void __launch_bounds__(256)
sn_mvWu_f(const float* __restrict__ W, const float* __restrict__ u, float* __restrict__ out,
          int normIn)
{
    int z = blockIdx.y;
    const float* uz = u + z * P_;
    float inv = 1.f;
    {
        float s = 0.f;
        for (int i = threadIdx.x; i < P_; i += 256) { float x = uz[i]; s += x * x; }
        s = blockReduceSum(s);
        if (normIn) inv = 1.f / (sqrtf(s) + 1e-12f);
    }
    const float* Wz = W + (size_t)z * P_ * H2_;
    int warp = threadIdx.x >> 5, lane = threadIdx.x & 31;
    int row = blockIdx.x * 8 + warp;
    const float* wr = Wz + (size_t)row * H2_;
    float s = 0.f;
    for (int k = lane; k < H2_; k += 32) s += wr[k] * (uz[k] * inv);
    #pragma unroll
    for (int o = 16; o; o >>= 1) s += __shfl_xor_sync(0xffffffffu, s, o);
    if (lane == 0) out[z * P_ + row] = s;
}
__global__ void __launch_bounds__(256)
sn_mvWTv_part(const float* __restrict__ W, const float* __restrict__ v, float* __restrict__ part)
{
    __shared__ float vs[256];
    int z = blockIdx.z, rc = blockIdx.y;
    const float* vz = v + z * P_;
    float inv;
    {
        float s = 0.f;
        for (int i = threadIdx.x; i < P_; i += 256) { float x = vz[i]; s += x * x; }
        s = blockReduceSum(s);
        inv = 1.f / (sqrtf(s) + 1e-12f);
    }
    int i0 = rc * 256;
    vs[threadIdx.x] = vz[i0 + threadIdx.x] * inv;
    __syncthreads();
    const float* Wz = W + (size_t)z * P_ * H2_;
    int j = blockIdx.x * 256 + threadIdx.x;
    float s = 0.f;
    #pragma unroll 8
    for (int i = 0; i < 256; i++) s += Wz[(size_t)(i0 + i) * H2_ + j] * vs[i];
    part[(size_t)(z * 8 + rc) * H2_ + j] = s;
}
__global__ void __launch_bounds__(256)
sn_mvWTv_red(const float* __restrict__ part, float* __restrict__ out)
{
    int z = blockIdx.y;
    int j = blockIdx.x * 256 + threadIdx.x;
    float s = 0.f;
    #pragma unroll
    for (int rc = 0; rc < 8; rc++) s += part[(size_t)(z * 8 + rc) * H2_ + j];
    out[z * P_ + j] = s;
}
__global__ void __launch_bounds__(256)
sn_sigma_f(const float* __restrict__ v, const float* __restrict__ t)
{
    int z = blockIdx.x;
    const float* vz = v + z * P_;
    float inv;
    {
        float s = 0.f;
        for (int i = threadIdx.x; i < P_; i += 256) { float x = vz[i]; s += x * x; }
        s = blockReduceSum(s);
        inv = 1.f / (sqrtf(s) + 1e-12f);
    }
    float s = 0.f;
    for (int i = threadIdx.x; i < P_; i += 256) s += (vz[i] * inv) * t[z * P_ + i];
    s = blockReduceSum(s);
    if (threadIdx.x == 0) d_sigma_inv[z] = 1.f / s;
}

// ---------------- fused wave stage (mag row-major) ----------------
__global__ void __launch_bounds__(256)
wave_k(const float* __restrict__ out2,
       const float* __restrict__ gw, const float* __restrict__ betaw,
       const float* __restrict__ phases, const float* __restrict__ temp,
       float* __restrict__ supr, float* __restrict__ supi, float* __restrict__ magRM)
{
    __shared__ float zbuf[H2_];
    __shared__ float wr[NW_][H_];
    __shared__ float wi[NW_][H_];
    __shared__ float mr[H_];
    const int b = blockIdx.x, tid = threadIdx.x;

    for (int s = 0; s < NW_; s++) {
        const float* row = out2 + ((size_t)b * NW_ + s) * H2_;
        float x[8];
        float sm = 0.f;
        #pragma unroll
        for (int t = 0; t < 8; t++) { x[t] = row[tid + t * 256]; sm += x[t]; }
        float mean = blockReduceSum(sm) * (1.f / (float)H2_);
        float vs = 0.f;
        #pragma unroll
        for (int t = 0; t < 8; t++) { float d = x[t] - mean; vs += d * d; }
        float var = blockReduceSum(vs) * (1.f / (float)H2_);
        float inv = rsqrtf(var + 1e-5f);
        float nsq = 0.f;
        #pragma unroll
        for (int t = 0; t < 8; t++) {
            int j = tid + t * 256;
            float y = (x[t] - mean) * inv * gw[s * H2_ + j] + betaw[s * H2_ + j];
            float zz = expf(-y * y);
            zbuf[j] = zz;
            nsq += zz * zz;
        }
        nsq = blockReduceSum(nsq) + 1e-8f;
        float factor = sqrtf(2.25f / nsq);
        float ph = phases[s];
        float c = cosf(ph), sn = sinf(ph);
        #pragma unroll
        for (int t = 0; t < 4; t++) {
            int h = tid + t * 256;
            float a  = zbuf[h] * factor;
            float be = zbuf[h + H_] * factor;
            wr[s][h] = a * c - be * sn;
            wi[s][h] = a * sn + be * c;
        }
        __syncthreads();
    }
    #pragma unroll
    for (int t = 0; t < 4; t++) {
        int h = tid + t * 256;
        mr[h] = (wr[0][h] + wr[1][h] + wr[2][h]) * (1.f / 3.f);
    }
    __syncthreads();
    float mn = 0.f, n0 = 0.f, n1 = 0.f, n2 = 0.f, d0 = 0.f, d1 = 0.f, d2 = 0.f;
    #pragma unroll
    for (int t = 0; t < 4; t++) {
        int h = tid + t * 256;
        float m = mr[h]; mn += m * m;
        float a0 = wr[0][h]; n0 += a0 * a0; d0 += a0 * m;
        float a1 = wr[1][h]; n1 += a1 * a1; d1 += a1 * m;
        float a2 = wr[2][h]; n2 += a2 * a2; d2 += a2 * m;
    }
    mn = blockReduceSum(mn);
    n0 = blockReduceSum(n0); n1 = blockReduceSum(n1); n2 = blockReduceSum(n2);
    d0 = blockReduceSum(d0); d1 = blockReduceSum(d1); d2 = blockReduceSum(d2);

    float mean_norm = sqrtf(mn) + 1e-8f;
    float cs0 = d0 / ((sqrtf(n0) + 1e-8f) * mean_norm);
    float cs1 = d1 / ((sqrtf(n1) + 1e-8f) * mean_norm);
    float cs2 = d2 / ((sqrtf(n2) + 1e-8f) * mean_norm);
    float invT = 1.f / temp[0];
    float l0 = cs0 * invT, l1 = cs1 * invT, l2 = cs2 * invT;
    float mx = fmaxf(l0, fmaxf(l1, l2));
    float e0 = expf(l0 - mx), e1 = expf(l1 - mx), e2 = expf(l2 - mx);
    float es = e0 + e1 + e2;
    float w0 = e0 / es, w1 = e1 / es, w2 = e2 / es;

    #pragma unroll
    for (int t = 0; t < 4; t++) {
        int h = tid + t * 256;
        float r  = wr[0][h] * w0 + wr[1][h] * w1 + wr[2][h] * w2;
        float ii = wi[0][h] * w0 + wi[1][h] * w1 + wi[2][h] * w2;
        size_t idx = (size_t)b * H_ + h;
        supr[idx] = r;
        supi[idx] = ii;
        magRM[idx] = sqrtf(r * r + ii * ii + 1e-8f);
    }
}

// ---------------- top-8 + sparse head fused ----------------
__global__ void __launch_bounds__(256)
topk_head_k(const float* __restrict__ supr, const float* __restrict__ supi,
            const float* __restrict__ W1, const float* __restrict__ b1,
            float* __restrict__ t1)
{
    __shared__ float val[H_];
    __shared__ float s_bv[8];
    __shared__ int   s_bi[8];
    __shared__ int   sel_i[8];
    __shared__ float sel_v[8];
    __shared__ float s_sum;
    const int b = blockIdx.x, tid = threadIdx.x;
    const int lane = tid & 31, wid = tid >> 5;

    #pragma unroll
    for (int t = 0; t < 4; t++) {
        int h = tid + t * 256;
        size_t idx = (size_t)b * H_ + h;
        float r = supr[idx], ii = supi[idx];
        val[h] = r * r + ii * ii;
    }
    if (tid == 0) s_sum = 0.f;
    __syncthreads();

    for (int it = 0; it < 8; it++) {
        float bv = -2.f; int bi = 1 << 30;
        #pragma unroll
        for (int t = 0; t < 4; t++) {
            int h = tid + t * 256;
            float v = val[h];
            if (v > bv) { bv = v; bi = h; }
        }
        #pragma unroll
        for (int o = 16; o; o >>= 1) {
            float ov = __shfl_xor_sync(0xffffffffu, bv, o);
            int   oi = __shfl_xor_sync(0xffffffffu, bi, o);
            if (ov > bv || (ov == bv && oi < bi)) { bv = ov; bi = oi; }
        }
        if (lane == 0) { s_bv[wid] = bv; s_bi[wid] = bi; }
        __syncthreads();
        if (tid == 0) {
            for (int q = 1; q < 8; q++)
                if (s_bv[q] > bv || (s_bv[q] == bv && s_bi[q] < bi)) { bv = s_bv[q]; bi = s_bi[q]; }
            sel_i[it] = bi; sel_v[it] = bv;
            s_sum += bv;
            val[bi] = -1.f;
        }
        __syncthreads();
    }

    float inv = 1.f / (s_sum + 1e-8f);
    int c0 = tid * 4;
    float a0 = b1[c0], a1 = b1[c0 + 1], a2 = b1[c0 + 2], a3 = b1[c0 + 3];
    #pragma unroll
    for (int j = 0; j < 8; j++) {
        float w = sel_v[j] * inv;
        const float* r = W1 + (size_t)sel_i[j] * H_ + c0;
        a0 = fmaf(w, r[0], a0);
        a1 = fmaf(w, r[1], a1);
        a2 = fmaf(w, r[2], a2);
        a3 = fmaf(w, r[3], a3);
    }
    size_t o = (size_t)b * H_ + c0;
    t1[o + 0] = gelu_f(a0);
    t1[o + 1] = gelu_f(a1);
    t1[o + 2] = gelu_f(a2);
    t1[o + 3] = gelu_f(a3);
}

// ---------------- launch ----------------
static inline unsigned pgrid(int ntiles) { return (unsigned)(ntiles < NCTA ? ntiles : NCTA); }

extern "C" void kernel_launch(void* const* d_in, const int* in_sizes, int n_in,
                              void* d_out, int out_size)
{
    const float* x      = (const float*)d_in[0];
    const float* Wp     = (const float*)d_in[1];
    const float* bp     = (const float*)d_in[2];
    const float* gp     = (const float*)d_in[3];
    const float* betap  = (const float*)d_in[4];
    const float* Ww     = (const float*)d_in[5];
    const float* bw     = (const float*)d_in[6];
    const float* gw     = (const float*)d_in[7];
    const float* betaw  = (const float*)d_in[8];
    const float* temp   = (const float*)d_in[9];
    const float* phases = (const float*)d_in[10];
    const float* Wg     = (const float*)d_in[11];
    const float* bg     = (const float*)d_in[12];
    const float* W1     = (const float*)d_in[13];
    const float* b1     = (const float*)d_in[14];
    const float* W2     = (const float*)d_in[15];
    const float* b2     = (const float*)d_in[16];
    float* out = (float*)d_out;

    static cudaStream_t s2 = nullptr;
    static cudaEvent_t evA = nullptr, evB = nullptr;
    if (s2 == nullptr) {
        cudaStreamCreateWithFlags(&s2, cudaStreamNonBlocking);
        cudaEventCreateWithFlags(&evA, cudaEventDisableTiming);
        cudaEventCreateWithFlags(&evB, cudaEventDisableTiming);
        cudaFuncSetAttribute(sgemm<0>, cudaFuncAttributeMaxDynamicSharedMemorySize, SG_SMEM);
        cudaFuncSetAttribute(sgemm<1>, cudaFuncAttributeMaxDynamicSharedMemorySize, SG_SMEM);
        cudaFuncSetAttribute(sgemm<2>, cudaFuncAttributeMaxDynamicSharedMemorySize, SG_SMEM);
        cudaFuncSetAttribute(sgemm<4>, cudaFuncAttributeMaxDynamicSharedMemorySize, SG_SMEM);
    }

    float *pXT, *pH, *pHT, *pOut2, *pSr, *pSi, *pMa, *pMb, *pMaT, *pMbT, *pT1, *pT1T, *pW2p;
    float *pU, *pV, *pT, *pPart;
    cudaGetSymbolAddress((void**)&pXT,   d_xT);
    cudaGetSymbolAddress((void**)&pH,    d_h);
    cudaGetSymbolAddress((void**)&pHT,   d_hT);
    cudaGetSymbolAddress((void**)&pOut2, d_out2);
    cudaGetSymbolAddress((void**)&pSr,   d_supr);
    cudaGetSymbolAddress((void**)&pSi,   d_supi);
    cudaGetSymbolAddress((void**)&pMa,   d_magA);
    cudaGetSymbolAddress((void**)&pMb,   d_magB);
    cudaGetSymbolAddress((void**)&pMaT,  d_magAT);
    cudaGetSymbolAddress((void**)&pMbT,  d_magBT);
    cudaGetSymbolAddress((void**)&pT1,   d_t1);
    cudaGetSymbolAddress((void**)&pT1T,  d_t1T);
    cudaGetSymbolAddress((void**)&pW2p,  d_W2p);
    cudaGetSymbolAddress((void**)&pU,    d_su);
    cudaGetSymbolAddress((void**)&pV,    d_sv);
    cudaGetSymbolAddress((void**)&pT,    d_st);
    cudaGetSymbolAddress((void**)&pPart, d_snp);

    // ---- fork: spectral chain + padW2 on side stream (depends only on Ww / W2) ----
    cudaEventRecord(evA, 0);
    cudaStreamWaitEvent(s2, evA, 0);
    sn_init_k<<<dim3(P_ / 256, NW_), 256, 0, s2>>>(pU);
    for (int it = 0; it < 5; it++) {
        sn_mvWu_f    <<<dim3(P_ / 8, NW_), 256, 0, s2>>>(Ww, pU, pV, it > 0);
        sn_mvWTv_part<<<dim3(H2_ / 256, 8, NW_), 256, 0, s2>>>(Ww, pV, pPart);
        sn_mvWTv_red <<<dim3(H2_ / 256, NW_), 256, 0, s2>>>(pPart, pU);
    }
    sn_mvWu_f<<<dim3(P_ / 8, NW_), 256, 0, s2>>>(Ww, pU, pT, 1);
    sn_sigma_f<<<NW_, 256, 0, s2>>>(pV, pT);
    padW2_k<<<(1024 * 1024) / 256, 256, 0, s2>>>(W2, pW2p);
    cudaEventRecord(evB, s2);

    // ---- main stream: GEMM1 path (concurrent with spectral) ----
    transpose_k<<<dim3(IN_ / 32, B_ / 32), 256>>>(x, pXT, B_, IN_);
    sgemm<0><<<pgrid(1024), 256, SG_SMEM>>>(
        pXT, B_, Wp, P_, 0, bp, 0, pH, P_, 0, IN_,
        nullptr, nullptr, nullptr, 0, 16, 64, 1024);
    ln_gelu_k<<<B_, 256>>>(pH, gp, betap);
    transpose_k<<<dim3(P_ / 32, B_ / 32), 256>>>(pH, pHT, B_, P_);

    // ---- join: wave GEMM needs sigma_inv ----
    cudaStreamWaitEvent(0, evB, 0);

    // 4) wave GEMM (sigma folded)
    sgemm<1><<<pgrid(3072), 256, SG_SMEM>>>(
        pHT, B_, Ww, H2_, (long long)P_ * H2_, bw, H2_, pOut2, NW_ * H2_, H2_, P_,
        nullptr, nullptr, nullptr, 0, 16, 64, 3072);

    // 5) fused wave stage
    wave_k<<<B_, 256>>>(pOut2, gw, betaw, phases, temp, pSr, pSi, pMa);

    // 6) two gate steps
    transpose_k<<<dim3(H_ / 32, B_ / 32), 256>>>(pMa, pMaT, B_, H_);
    sgemm<2><<<pgrid(512), 256, SG_SMEM>>>(
        pMaT, B_, Wg, H_, 0, bg, 0, nullptr, H_, 0, H_,
        pSr, pSi, pMb, 0, 8, 64, 512);
    transpose_k<<<dim3(H_ / 32, B_ / 32), 256>>>(pMb, pMbT, B_, H_);
    sgemm<2><<<pgrid(512), 256, SG_SMEM>>>(
        pMbT, B_, Wg, H_, 0, bg, 0, nullptr, H_, 0, H_,
        pSr, pSi, pMa, 0, 8, 64, 512);

    // 7) top-8 + sparse head
    topk_head_k<<<B_, 256>>>(pSr, pSi, W1, b1, pT1);
    transpose_k<<<dim3(H_ / 32, B_ / 32), 256>>>(pT1, pT1T, B_, H_);

    // 8) final GEMM
    sgemm<4><<<pgrid(512), 256, SG_SMEM>>>(
        pT1T, B_, pW2p, 1024, 0, b2, 0, out, NC_, 0, H_,
        nullptr, nullptr, nullptr, NC_, 8, 64, 512);
}

// round 16
// speedup vs baseline: 1.0338x; 1.0338x over previous
#include <cuda_runtime.h>
#include <math.h>
#include <stdint.h>

#define B_   8192
#define IN_  4096
#define H_   1024
#define P_   2048
#define NW_  3
#define NC_  1000
#define H2_  2048

// ---------------- scratch ----------------
__device__ float d_xT  [(size_t)IN_ * B_];
__device__ float d_h   [(size_t)B_ * P_];
__device__ float d_hT  [(size_t)P_ * B_];
__device__ float d_out2[(size_t)B_ * NW_ * H2_];
__device__ float d_supr[(size_t)B_ * H_];
__device__ float d_supi[(size_t)B_ * H_];
__device__ float d_magA[(size_t)B_ * H_];
__device__ float d_magB[(size_t)B_ * H_];
__device__ float d_magAT[(size_t)H_ * B_];
__device__ float d_magBT[(size_t)H_ * B_];
__device__ float d_t1  [(size_t)B_ * H_];
__device__ float d_t1T [(size_t)H_ * B_];
__device__ float d_W2p [(size_t)H_ * 1024];
__device__ float d_su[NW_ * P_];
__device__ float d_sv[NW_ * P_];
__device__ float d_st[NW_ * P_];
__device__ float d_snp[NW_ * 8 * H2_];
__device__ float d_sigma_inv[NW_];

// ---------------- helpers ----------------
__device__ __forceinline__ uint32_t smem_u32(const void* p) {
    uint32_t a;
    asm("{ .reg .u64 t; cvta.to.shared.u64 t, %1; cvt.u32.u64 %0, t; }" : "=r"(a) : "l"(p));
    return a;
}
__device__ __forceinline__ void cp16(uint32_t dst, const void* src) {
    asm volatile("cp.async.cg.shared.global [%0], [%1], 16;\n" :: "r"(dst), "l"(src));
}
#define CP_COMMIT() asm volatile("cp.async.commit_group;\n")
#define CP_WAIT1()  asm volatile("cp.async.wait_group 1;\n" ::: "memory")
#define CP_WAIT0()  asm volatile("cp.async.wait_group 0;\n" ::: "memory")

__device__ __forceinline__ void ffma2(unsigned long long& acc, unsigned long long a,
                                      unsigned long long b) {
    asm("fma.rn.f32x2 %0, %1, %2, %0;" : "+l"(acc) : "l"(a), "l"(b));
}
__device__ __forceinline__ unsigned long long dup2(float v) {
    unsigned long long r;
    asm("mov.b64 %0, {%1, %1};" : "=l"(r) : "f"(v));
    return r;
}
__device__ __forceinline__ void upk2(unsigned long long v, float& lo, float& hi) {
    asm("mov.b64 {%0, %1}, %2;" : "=f"(lo), "=f"(hi) : "l"(v));
}
__device__ __forceinline__ float gelu_f(float x) {
    return 0.5f * x * (1.f + erff(x * 0.70710678118654752440f));
}
__device__ __forceinline__ float blockReduceSum(float v) {
    __shared__ float sh[33];
    int lane = threadIdx.x & 31, wid = threadIdx.x >> 5;
    #pragma unroll
    for (int o = 16; o; o >>= 1) v += __shfl_xor_sync(0xffffffffu, v, o);
    __syncthreads();
    if (lane == 0) sh[wid] = v;
    __syncthreads();
    if (wid == 0) {
        int nw = (blockDim.x + 31) >> 5;
        float r = (lane < nw) ? sh[lane] : 0.f;
        #pragma unroll
        for (int o = 16; o; o >>= 1) r += __shfl_xor_sync(0xffffffffu, r, o);
        if (lane == 0) sh[32] = r;
    }
    __syncthreads();
    return sh[32];
}

// ---------------- persistent SGEMM, cross-tile continuous cp.async pipeline ----------------
// C[M,N] = A[M,K] @ B[K,N]; A given transposed (AT [K][M], ld=ldA); B row-major [K][N].
// Tile 128x128x32, 3 stages; next tile's first stages prefetched under current epilogue.
// Per-element FMA order k-ascending -> bit-identical outputs vs R11/R12.
// EPI: 0 +bias store ; 1 *sigma_inv[z]+bias ; 2 sigmoid gate update ; 4 +bias col<Nreal
#define SG_SMEM 98304
#define NCTA 296

template<int EPI>
__global__ void __launch_bounds__(256, 2)
sgemm(const float* __restrict__ AT, int ldA,
      const float* __restrict__ Bm, int ldB, long long bZ,
      const float* __restrict__ bias, long long biasZ,
      float* __restrict__ C, int ldc, long long cZ,
      int K,
      float* __restrict__ supr, float* __restrict__ supi,
      float* __restrict__ magRM, int Nreal,
      int gx, int gy, int ntiles)
{
    extern __shared__ float smf[];
    float* As = smf;                 // [3][32][128]
    float* Bs = smf + 3 * 32 * 128;  // [3][32][128]
    const int tid = threadIdx.x;
    const int tr = (tid >> 4) * 8;
    const int tc = (tid & 15) * 4;
    const uint32_t sA = smem_u32(As);
    const uint32_t sB = smem_u32(Bs);
    const int nit = K / 32;          // >= 2 for all our GEMMs

    int t = blockIdx.x;
    if (t >= ntiles) return;

    auto load_stage = [&](int st, int k0, int br, int bc, const float* Bp) {
        #pragma unroll
        for (int j = 0; j < 4; j++) {
            int c = tid + j * 256;
            int kr = c >> 5, sg = c & 31;
            cp16(sA + st * 16384 + kr * 512 + sg * 16,
                 AT + (size_t)(k0 + kr) * ldA + br + sg * 4);
            cp16(sB + st * 16384 + kr * 512 + sg * 16,
                 Bp + (size_t)(k0 + kr) * ldB + bc + sg * 4);
        }
    };

    int brow, bcol;
    const float* Bz;
    {
        int tx = t % gx, rem = t / gx;
        brow = (rem % gy) * 128; bcol = tx * 128;
        Bz = Bm + (size_t)(rem / gy) * bZ;
    }

    load_stage(0, 0, brow, bcol, Bz);  CP_COMMIT();
    load_stage(1, 32, brow, bcol, Bz); CP_COMMIT();
    int stg = 0;

    while (true) {
        const int tn = t + gridDim.x;
        int brow2 = 0, bcol2 = 0;
        const float* Bz2 = Bm;
        const bool hasNext = (tn < ntiles);
        if (hasNext) {
            int tx = tn % gx, rem = tn / gx;
            brow2 = (rem % gy) * 128; bcol2 = tx * 128;
            Bz2 = Bm + (size_t)(rem / gy) * bZ;
        }

        unsigned long long acc[4][8];
        #pragma unroll
        for (int i = 0; i < 4; i++)
            #pragma unroll
            for (int j = 0; j < 8; j++) acc[i][j] = 0ull;

        for (int it = 0; it < nit; ++it) {
            CP_WAIT1();
            __syncthreads();
            int s2 = stg + 2; if (s2 >= 3) s2 -= 3;
            int ps = it + 2;
            if (ps < nit)       load_stage(s2, ps * 32, brow, bcol, Bz);
            else if (hasNext)   load_stage(s2, (ps - nit) * 32, brow2, bcol2, Bz2);
            CP_COMMIT();

            const float* Ab = As + stg * 4096;
            const float* Bb = Bs + stg * 4096;
            #pragma unroll
            for (int kk = 0; kk < 32; kk++) {
                ulonglong2 av0 = *(const ulonglong2*)(Ab + kk * 128 + tr);
                ulonglong2 av1 = *(const ulonglong2*)(Ab + kk * 128 + tr + 4);
                float4 b0 = *(const float4*)(Bb + kk * 128 + tc);
                float4 b1 = *(const float4*)(Bb + kk * 128 + tc + 64);
                unsigned long long bd[8];
                bd[0] = dup2(b0.x); bd[1] = dup2(b0.y); bd[2] = dup2(b0.z); bd[3] = dup2(b0.w);
                bd[4] = dup2(b1.x); bd[5] = dup2(b1.y); bd[6] = dup2(b1.z); bd[7] = dup2(b1.w);
                unsigned long long ap[4] = { av0.x, av0.y, av1.x, av1.y };
                #pragma unroll
                for (int i = 0; i < 4; i++)
                    #pragma unroll
                    for (int j = 0; j < 8; j++)
                        ffma2(acc[i][j], ap[i], bd[j]);
            }
            stg = stg + 1; if (stg >= 3) stg -= 3;
        }

        // epilogue (overlaps with next tile's in-flight stage loads)
        {
            const int z = t / (gx * gy);
            const float* biasz = bias + (size_t)z * biasZ;
            const float scale = (EPI == 1) ? d_sigma_inv[z] : 1.f;
            float* Cz = C + (size_t)z * cZ;

            #pragma unroll
            for (int i = 0; i < 4; i++) {
                float vlo[8], vhi[8];
                #pragma unroll
                for (int j = 0; j < 8; j++) upk2(acc[i][j], vlo[j], vhi[j]);
                #pragma unroll
                for (int half = 0; half < 2; half++) {
                    int row = brow + tr + 2 * i + half;
                    const float* vv = half ? vhi : vlo;
                    #pragma unroll
                    for (int g = 0; g < 2; g++) {
                        int col = bcol + tc + g * 64;
                        if (EPI != 2) {
                            if (EPI == 4 && col >= Nreal) continue;
                            float4 o;
                            o.x = vv[g*4+0] * scale + biasz[col + 0];
                            o.y = vv[g*4+1] * scale + biasz[col + 1];
                            o.z = vv[g*4+2] * scale + biasz[col + 2];
                            o.w = vv[g*4+3] * scale + biasz[col + 3];
                            *(float4*)(Cz + (size_t)row * ldc + col) = o;
                        } else {
                            #pragma unroll
                            for (int q = 0; q < 4; q++) {
                                int cc = col + q;
                                float v = vv[g*4+q] + biasz[cc];
                                float gt = 1.f / (1.f + expf(-v)) + 0.1f;
                                size_t idx = (size_t)row * ldc + cc;
                                float rr = supr[idx] * gt, ii = supi[idx] * gt;
                                supr[idx] = rr; supi[idx] = ii;
                                magRM[idx] = sqrtf(rr * rr + ii * ii + 1e-8f);
                            }
                        }
                    }
                }
            }
        }

        if (!hasNext) break;
        t = tn; brow = brow2; bcol = bcol2; Bz = Bz2;
    }
    CP_WAIT0();   // drain residual groups before exit
}

// ---------------- preprocessing ----------------
__global__ void __launch_bounds__(256)
transpose_k(const float* __restrict__ src, float* __restrict__ dst, int R, int C)
{
    __shared__ float t[32][33];
    int r0 = blockIdx.y * 32, c0 = blockIdx.x * 32;
    int tx = threadIdx.x & 31, ty = threadIdx.x >> 5;
    #pragma unroll
    for (int i = 0; i < 4; i++)
        t[ty + i * 8][tx] = src[(size_t)(r0 + ty + i * 8) * C + c0 + tx];
    __syncthreads();
    #pragma unroll
    for (int i = 0; i < 4; i++)
        dst[(size_t)(c0 + ty + i * 8) * R + r0 + tx] = t[tx][ty + i * 8];
}

__global__ void __launch_bounds__(256)
padW2_k(const float* __restrict__ W2, float* __restrict__ W2p)
{
    int i = blockIdx.x * 256 + threadIdx.x;
    int k = i >> 10, n = i & 1023;
    W2p[i] = (n < NC_) ? W2[(size_t)k * NC_ + n] : 0.f;
}

// LN + gelu, in place (row-major)
__global__ void __launch_bounds__(256)
ln_gelu_k(float* __restrict__ h, const float* __restrict__ g, const float* __restrict__ beta)
{
    const int b = blockIdx.x, tid = threadIdx.x;
    float* row = h + (size_t)b * P_;
    float x[8];
    float sm = 0.f;
    #pragma unroll
    for (int t = 0; t < 8; t++) { x[t] = row[tid + t * 256]; sm += x[t]; }
    float mean = blockReduceSum(sm) * (1.f / (float)P_);
    float vs = 0.f;
    #pragma unroll
    for (int t = 0; t < 8; t++) { float d = x[t] - mean; vs += d * d; }
    float var = blockReduceSum(vs) * (1.f / (float)P_);
    float inv = rsqrtf(var + 1e-5f);
    #pragma unroll
    for (int t = 0; t < 8; t++) {
        int j = tid + t * 256;
        float y = (x[t] - mean) * inv * g[j] + beta[j];
        row[j] = gelu_f(y);
    }
}

// ---------------- spectral normalization ----------------
__global__ void sn_init_k(float* __restrict__ u) {
    int z = blockIdx.y;
    int j = blockIdx.x * 256 + threadIdx.x;
    u[z * P_ + j] = 1.f / sqrtf((float)P_);
}
__global__ void __launch_bounds__(256)
sn_mvWu_f(const float* __restrict__ W, const float* __restrict__ u, float* __restrict__ out,
          int normIn)
{
    int z = blockIdx.y;
    const float* uz = u + z * P_;
    float inv = 1.f;
    {
        float s = 0.f;
        for (int i = threadIdx.x; i < P_; i += 256) { float x = uz[i]; s += x * x; }
        s = blockReduceSum(s);
        if (normIn) inv = 1.f / (sqrtf(s) + 1e-12f);
    }
    const float* Wz = W + (size_t)z * P_ * H2_;
    int warp = threadIdx.x >> 5, lane = threadIdx.x & 31;
    int row = blockIdx.x * 8 + warp;
    const float* wr = Wz + (size_t)row * H2_;
    float s = 0.f;
    for (int k = lane; k < H2_; k += 32) s += wr[k] * (uz[k] * inv);
    #pragma unroll
    for (int o = 16; o; o >>= 1) s += __shfl_xor_sync(0xffffffffu, s, o);
    if (lane == 0) out[z * P_ + row] = s;
}
__global__ void __launch_bounds__(256)
sn_mvWTv_part(const float* __restrict__ W, const float* __restrict__ v, float* __restrict__ part)
{
    __shared__ float vs[256];
    int z = blockIdx.z, rc = blockIdx.y;
    const float* vz = v + z * P_;
    float inv;
    {
        float s = 0.f;
        for (int i = threadIdx.x; i < P_; i += 256) { float x = vz[i]; s += x * x; }
        s = blockReduceSum(s);
        inv = 1.f / (sqrtf(s) + 1e-12f);
    }
    int i0 = rc * 256;
    vs[threadIdx.x] = vz[i0 + threadIdx.x] * inv;
    __syncthreads();
    const float* Wz = W + (size_t)z * P_ * H2_;
    int j = blockIdx.x * 256 + threadIdx.x;
    float s = 0.f;
    #pragma unroll 8
    for (int i = 0; i < 256; i++) s += Wz[(size_t)(i0 + i) * H2_ + j] * vs[i];
    part[(size_t)(z * 8 + rc) * H2_ + j] = s;
}
__global__ void __launch_bounds__(256)
sn_mvWTv_red(const float* __restrict__ part, float* __restrict__ out)
{
    int z = blockIdx.y;
    int j = blockIdx.x * 256 + threadIdx.x;
    float s = 0.f;
    #pragma unroll
    for (int rc = 0; rc < 8; rc++) s += part[(size_t)(z * 8 + rc) * H2_ + j];
    out[z * P_ + j] = s;
}
__global__ void __launch_bounds__(256)
sn_sigma_f(const float* __restrict__ v, const float* __restrict__ t)
{
    int z = blockIdx.x;
    const float* vz = v + z * P_;
    float inv;
    {
        float s = 0.f;
        for (int i = threadIdx.x; i < P_; i += 256) { float x = vz[i]; s += x * x; }
        s = blockReduceSum(s);
        inv = 1.f / (sqrtf(s) + 1e-12f);
    }
    float s = 0.f;
    for (int i = threadIdx.x; i < P_; i += 256) s += (vz[i] * inv) * t[z * P_ + i];
    s = blockReduceSum(s);
    if (threadIdx.x == 0) d_sigma_inv[z] = 1.f / s;
}

// ---------------- fused wave stage (mag row-major) ----------------
__global__ void __launch_bounds__(256)
wave_k(const float* __restrict__ out2,
       const float* __restrict__ gw, const float* __restrict__ betaw,
       const float* __restrict__ phases, const float* __restrict__ temp,
       float* __restrict__ supr, float* __restrict__ supi, float* __restrict__ magRM)
{
    __shared__ float zbuf[H2_];
    __shared__ float wr[NW_][H_];
    __shared__ float wi[NW_][H_];
    __shared__ float mr[H_];
    const int b = blockIdx.x, tid = threadIdx.x;

    for (int s = 0; s < NW_; s++) {
        const float* row = out2 + ((size_t)b * NW_ + s) * H2_;
        float x[8];
        float sm = 0.f;
        #pragma unroll
        for (int t = 0; t < 8; t++) { x[t] = row[tid + t * 256]; sm += x[t]; }
        float mean = blockReduceSum(sm) * (1.f / (float)H2_);
        float vs = 0.f;
        #pragma unroll
        for (int t = 0; t < 8; t++) { float d = x[t] - mean; vs += d * d; }
        float var = blockReduceSum(vs) * (1.f / (float)H2_);
        float inv = rsqrtf(var + 1e-5f);
        float nsq = 0.f;
        #pragma unroll
        for (int t = 0; t < 8; t++) {
            int j = tid + t * 256;
            float y = (x[t] - mean) * inv * gw[s * H2_ + j] + betaw[s * H2_ + j];
            float zz = expf(-y * y);
            zbuf[j] = zz;
            nsq += zz * zz;
        }
        nsq = blockReduceSum(nsq) + 1e-8f;
        float factor = sqrtf(2.25f / nsq);
        float ph = phases[s];
        float c = cosf(ph), sn = sinf(ph);
        #pragma unroll
        for (int t = 0; t < 4; t++) {
            int h = tid + t * 256;
            float a  = zbuf[h] * factor;
            float be = zbuf[h + H_] * factor;
            wr[s][h] = a * c - be * sn;
            wi[s][h] = a * sn + be * c;
        }
        __syncthreads();
    }
    #pragma unroll
    for (int t = 0; t < 4; t++) {
        int h = tid + t * 256;
        mr[h] = (wr[0][h] + wr[1][h] + wr[2][h]) * (1.f / 3.f);
    }
    __syncthreads();
    float mn = 0.f, n0 = 0.f, n1 = 0.f, n2 = 0.f, d0 = 0.f, d1 = 0.f, d2 = 0.f;
    #pragma unroll
    for (int t = 0; t < 4; t++) {
        int h = tid + t * 256;
        float m = mr[h]; mn += m * m;
        float a0 = wr[0][h]; n0 += a0 * a0; d0 += a0 * m;
        float a1 = wr[1][h]; n1 += a1 * a1; d1 += a1 * m;
        float a2 = wr[2][h]; n2 += a2 * a2; d2 += a2 * m;
    }
    mn = blockReduceSum(mn);
    n0 = blockReduceSum(n0); n1 = blockReduceSum(n1); n2 = blockReduceSum(n2);
    d0 = blockReduceSum(d0); d1 = blockReduceSum(d1); d2 = blockReduceSum(d2);

    float mean_norm = sqrtf(mn) + 1e-8f;
    float cs0 = d0 / ((sqrtf(n0) + 1e-8f) * mean_norm);
    float cs1 = d1 / ((sqrtf(n1) + 1e-8f) * mean_norm);
    float cs2 = d2 / ((sqrtf(n2) + 1e-8f) * mean_norm);
    float invT = 1.f / temp[0];
    float l0 = cs0 * invT, l1 = cs1 * invT, l2 = cs2 * invT;
    float mx = fmaxf(l0, fmaxf(l1, l2));
    float e0 = expf(l0 - mx), e1 = expf(l1 - mx), e2 = expf(l2 - mx);
    float es = e0 + e1 + e2;
    float w0 = e0 / es, w1 = e1 / es, w2 = e2 / es;

    #pragma unroll
    for (int t = 0; t < 4; t++) {
        int h = tid + t * 256;
        float r  = wr[0][h] * w0 + wr[1][h] * w1 + wr[2][h] * w2;
        float ii = wi[0][h] * w0 + wi[1][h] * w1 + wi[2][h] * w2;
        size_t idx = (size_t)b * H_ + h;
        supr[idx] = r;
        supi[idx] = ii;
        magRM[idx] = sqrtf(r * r + ii * ii + 1e-8f);
    }
}

// ---------------- top-8 + sparse head fused ----------------
__global__ void __launch_bounds__(256)
topk_head_k(const float* __restrict__ supr, const float* __restrict__ supi,
            const float* __restrict__ W1, const float* __restrict__ b1,
            float* __restrict__ t1)
{
    __shared__ float val[H_];
    __shared__ float s_bv[8];
    __shared__ int   s_bi[8];
    __shared__ int   sel_i[8];
    __shared__ float sel_v[8];
    __shared__ float s_sum;
    const int b = blockIdx.x, tid = threadIdx.x;
    const int lane = tid & 31, wid = tid >> 5;

    #pragma unroll
    for (int t = 0; t < 4; t++) {
        int h = tid + t * 256;
        size_t idx = (size_t)b * H_ + h;
        float r = supr[idx], ii = supi[idx];
        val[h] = r * r + ii * ii;
    }
    if (tid == 0) s_sum = 0.f;
    __syncthreads();

    for (int it = 0; it < 8; it++) {
        float bv = -2.f; int bi = 1 << 30;
        #pragma unroll
        for (int t = 0; t < 4; t++) {
            int h = tid + t * 256;
            float v = val[h];
            if (v > bv) { bv = v; bi = h; }
        }
        #pragma unroll
        for (int o = 16; o; o >>= 1) {
            float ov = __shfl_xor_sync(0xffffffffu, bv, o);
            int   oi = __shfl_xor_sync(0xffffffffu, bi, o);
            if (ov > bv || (ov == bv && oi < bi)) { bv = ov; bi = oi; }
        }
        if (lane == 0) { s_bv[wid] = bv; s_bi[wid] = bi; }
        __syncthreads();
        if (tid == 0) {
            for (int q = 1; q < 8; q++)
                if (s_bv[q] > bv || (s_bv[q] == bv && s_bi[q] < bi)) { bv = s_bv[q]; bi = s_bi[q]; }
            sel_i[it] = bi; sel_v[it] = bv;
            s_sum += bv;
            val[bi] = -1.f;
        }
        __syncthreads();
    }

    float inv = 1.f / (s_sum + 1e-8f);
    int c0 = tid * 4;
    float a0 = b1[c0], a1 = b1[c0 + 1], a2 = b1[c0 + 2], a3 = b1[c0 + 3];
    #pragma unroll
    for (int j = 0; j < 8; j++) {
        float w = sel_v[j] * inv;
        const float* r = W1 + (size_t)sel_i[j] * H_ + c0;
        a0 = fmaf(w, r[0], a0);
        a1 = fmaf(w, r[1], a1);
        a2 = fmaf(w, r[2], a2);
        a3 = fmaf(w, r[3], a3);
    }
    size_t o = (size_t)b * H_ + c0;
    t1[o + 0] = gelu_f(a0);
    t1[o + 1] = gelu_f(a1);
    t1[o + 2] = gelu_f(a2);
    t1[o + 3] = gelu_f(a3);
}

// ---------------- launch ----------------
static inline unsigned pgrid(int ntiles) { return (unsigned)(ntiles < NCTA ? ntiles : NCTA); }

extern "C" void kernel_launch(void* const* d_in, const int* in_sizes, int n_in,
                              void* d_out, int out_size)
{
    const float* x      = (const float*)d_in[0];
    const float* Wp     = (const float*)d_in[1];
    const float* bp     = (const float*)d_in[2];
    const float* gp     = (const float*)d_in[3];
    const float* betap  = (const float*)d_in[4];
    const float* Ww     = (const float*)d_in[5];
    const float* bw     = (const float*)d_in[6];
    const float* gw     = (const float*)d_in[7];
    const float* betaw  = (const float*)d_in[8];
    const float* temp   = (const float*)d_in[9];
    const float* phases = (const float*)d_in[10];
    const float* Wg     = (const float*)d_in[11];
    const float* bg     = (const float*)d_in[12];
    const float* W1     = (const float*)d_in[13];
    const float* b1     = (const float*)d_in[14];
    const float* W2     = (const float*)d_in[15];
    const float* b2     = (const float*)d_in[16];
    float* out = (float*)d_out;

    cudaFuncSetAttribute(sgemm<0>, cudaFuncAttributeMaxDynamicSharedMemorySize, SG_SMEM);
    cudaFuncSetAttribute(sgemm<1>, cudaFuncAttributeMaxDynamicSharedMemorySize, SG_SMEM);
    cudaFuncSetAttribute(sgemm<2>, cudaFuncAttributeMaxDynamicSharedMemorySize, SG_SMEM);
    cudaFuncSetAttribute(sgemm<4>, cudaFuncAttributeMaxDynamicSharedMemorySize, SG_SMEM);

    float *pXT, *pH, *pHT, *pOut2, *pSr, *pSi, *pMa, *pMb, *pMaT, *pMbT, *pT1, *pT1T, *pW2p;
    float *pU, *pV, *pT, *pPart;
    cudaGetSymbolAddress((void**)&pXT,   d_xT);
    cudaGetSymbolAddress((void**)&pH,    d_h);
    cudaGetSymbolAddress((void**)&pHT,   d_hT);
    cudaGetSymbolAddress((void**)&pOut2, d_out2);
    cudaGetSymbolAddress((void**)&pSr,   d_supr);
    cudaGetSymbolAddress((void**)&pSi,   d_supi);
    cudaGetSymbolAddress((void**)&pMa,   d_magA);
    cudaGetSymbolAddress((void**)&pMb,   d_magB);
    cudaGetSymbolAddress((void**)&pMaT,  d_magAT);
    cudaGetSymbolAddress((void**)&pMbT,  d_magBT);
    cudaGetSymbolAddress((void**)&pT1,   d_t1);
    cudaGetSymbolAddress((void**)&pT1T,  d_t1T);
    cudaGetSymbolAddress((void**)&pW2p,  d_W2p);
    cudaGetSymbolAddress((void**)&pU,    d_su);
    cudaGetSymbolAddress((void**)&pV,    d_sv);
    cudaGetSymbolAddress((void**)&pT,    d_st);
    cudaGetSymbolAddress((void**)&pPart, d_snp);

    // preprocessing
    transpose_k<<<dim3(IN_ / 32, B_ / 32), 256>>>(x, pXT, B_, IN_);
    padW2_k<<<(1024 * 1024) / 256, 256>>>(W2, pW2p);

    // 1) GEMM1: h = x @ Wp + bp
    sgemm<0><<<pgrid(1024), 256, SG_SMEM>>>(
        pXT, B_, Wp, P_, 0, bp, 0, pH, P_, 0, IN_,
        nullptr, nullptr, nullptr, 0, 16, 64, 1024);

    // 2) LN + gelu in place, then transpose to hT
    ln_gelu_k<<<B_, 256>>>(pH, gp, betap);
    transpose_k<<<dim3(P_ / 32, B_ / 32), 256>>>(pH, pHT, B_, P_);

    // 3) spectral normalization (serial, main stream) -> d_sigma_inv
    sn_init_k<<<dim3(P_ / 256, NW_), 256>>>(pU);
    for (int it = 0; it < 5; it++) {
        sn_mvWu_f    <<<dim3(P_ / 8, NW_), 256>>>(Ww, pU, pV, it > 0);
        sn_mvWTv_part<<<dim3(H2_ / 256, 8, NW_), 256>>>(Ww, pV, pPart);
        sn_mvWTv_red <<<dim3(H2_ / 256, NW_), 256>>>(pPart, pU);
    }
    sn_mvWu_f<<<dim3(P_ / 8, NW_), 256>>>(Ww, pU, pT, 1);
    sn_sigma_f<<<NW_, 256>>>(pV, pT);

    // 4) wave GEMM (sigma folded)
    sgemm<1><<<pgrid(3072), 256, SG_SMEM>>>(
        pHT, B_, Ww, H2_, (long long)P_ * H2_, bw, H2_, pOut2, NW_ * H2_, H2_, P_,
        nullptr, nullptr, nullptr, 0, 16, 64, 3072);

    // 5) fused wave stage
    wave_k<<<B_, 256>>>(pOut2, gw, betaw, phases, temp, pSr, pSi, pMa);

    // 6) two gate steps
    transpose_k<<<dim3(H_ / 32, B_ / 32), 256>>>(pMa, pMaT, B_, H_);
    sgemm<2><<<pgrid(512), 256, SG_SMEM>>>(
        pMaT, B_, Wg, H_, 0, bg, 0, nullptr, H_, 0, H_,
        pSr, pSi, pMb, 0, 8, 64, 512);
    transpose_k<<<dim3(H_ / 32, B_ / 32), 256>>>(pMb, pMbT, B_, H_);
    sgemm<2><<<pgrid(512), 256, SG_SMEM>>>(
        pMbT, B_, Wg, H_, 0, bg, 0, nullptr, H_, 0, H_,
        pSr, pSi, pMa, 0, 8, 64, 512);

    // 7) top-8 + sparse head
    topk_head_k<<<B_, 256>>>(pSr, pSi, W1, b1, pT1);
    transpose_k<<<dim3(H_ / 32, B_ / 32), 256>>>(pT1, pT1T, B_, H_);

    // 8) final GEMM
    sgemm<4><<<pgrid(512), 256, SG_SMEM>>>(
        pT1T, B_, pW2p, 1024, 0, b2, 0, out, NC_, 0, H_,
        nullptr, nullptr, nullptr, NC_, 8, 64, 512);
}

// round 17
// speedup vs baseline: 1.0534x; 1.0190x over previous
#include <cuda_runtime.h>
#include <math.h>
#include <stdint.h>

#define B_   8192
#define IN_  4096
#define H_   1024
#define P_   2048
#define NW_  3
#define NC_  1000
#define H2_  2048

// ---------------- scratch ----------------
__device__ float d_xT  [(size_t)IN_ * B_];
__device__ float d_h   [(size_t)B_ * P_];
__device__ float d_hT  [(size_t)P_ * B_];
__device__ float d_out2[(size_t)B_ * NW_ * H2_];
__device__ float d_supr[(size_t)B_ * H_];
__device__ float d_supi[(size_t)B_ * H_];
__device__ float d_magA[(size_t)B_ * H_];
__device__ float d_magB[(size_t)B_ * H_];
__device__ float d_magAT[(size_t)H_ * B_];
__device__ float d_magBT[(size_t)H_ * B_];
__device__ float d_t1  [(size_t)B_ * H_];
__device__ float d_t1T [(size_t)H_ * B_];
__device__ float d_W2p [(size_t)H_ * 1024];
__device__ float d_su[NW_ * P_];
__device__ float d_sv[NW_ * P_];
__device__ float d_st[NW_ * P_];
__device__ float d_snp[NW_ * 8 * H2_];
__device__ float d_sigma_inv[NW_];

// ---------------- helpers ----------------
__device__ __forceinline__ uint32_t smem_u32(const void* p) {
    uint32_t a;
    asm("{ .reg .u64 t; cvta.to.shared.u64 t, %1; cvt.u32.u64 %0, t; }" : "=r"(a) : "l"(p));
    return a;
}
__device__ __forceinline__ void cp16(uint32_t dst, const void* src) {
    asm volatile("cp.async.cg.shared.global [%0], [%1], 16;\n" :: "r"(dst), "l"(src));
}
#define CP_COMMIT() asm volatile("cp.async.commit_group;\n")
#define CP_WAIT1()  asm volatile("cp.async.wait_group 1;\n" ::: "memory")
#define CP_WAIT0()  asm volatile("cp.async.wait_group 0;\n" ::: "memory")

__device__ __forceinline__ void ffma2(unsigned long long& acc, unsigned long long a,
                                      unsigned long long b) {
    asm("fma.rn.f32x2 %0, %1, %2, %0;" : "+l"(acc) : "l"(a), "l"(b));
}
__device__ __forceinline__ unsigned long long dup2(float v) {
    unsigned long long r;
    asm("mov.b64 %0, {%1, %1};" : "=l"(r) : "f"(v));
    return r;
}
__device__ __forceinline__ void upk2(unsigned long long v, float& lo, float& hi) {
    asm("mov.b64 {%0, %1}, %2;" : "=f"(lo), "=f"(hi) : "l"(v));
}
__device__ __forceinline__ float gelu_f(float x) {
    return 0.5f * x * (1.f + erff(x * 0.70710678118654752440f));
}
__device__ __forceinline__ float blockReduceSum(float v) {
    __shared__ float sh[33];
    int lane = threadIdx.x & 31, wid = threadIdx.x >> 5;
    #pragma unroll
    for (int o = 16; o; o >>= 1) v += __shfl_xor_sync(0xffffffffu, v, o);
    __syncthreads();
    if (lane == 0) sh[wid] = v;
    __syncthreads();
    if (wid == 0) {
        int nw = (blockDim.x + 31) >> 5;
        float r = (lane < nw) ? sh[lane] : 0.f;
        #pragma unroll
        for (int o = 16; o; o >>= 1) r += __shfl_xor_sync(0xffffffffu, r, o);
        if (lane == 0) sh[32] = r;
    }
    __syncthreads();
    return sh[32];
}

// ---------------- persistent SGEMM (R12-proven: per-tile 3-stage BK=32 pipeline) ----------------
// C[M,N] = A[M,K] @ B[K,N]; A given transposed (AT [K][M], ld=ldA); B row-major [K][N].
// Tile 128x128x32, grid-stride over tiles. Per-element FMA order k-ascending (bit-identical).
// EPI: 0 +bias store ; 1 *sigma_inv[z]+bias ; 2 sigmoid gate update ; 4 +bias col<Nreal
#define SG_SMEM 98304
#define NCTA 296

template<int EPI>
__global__ void __launch_bounds__(256, 2)
sgemm(const float* __restrict__ AT, int ldA,
      const float* __restrict__ Bm, int ldB, long long bZ,
      const float* __restrict__ bias, long long biasZ,
      float* __restrict__ C, int ldc, long long cZ,
      int K,
      float* __restrict__ supr, float* __restrict__ supi,
      float* __restrict__ magRM, int Nreal,
      int gx, int gy, int ntiles)
{
    extern __shared__ float smf[];
    float* As = smf;                 // [3][32][128]
    float* Bs = smf + 3 * 32 * 128;  // [3][32][128]
    const int tid = threadIdx.x;
    const int tr = (tid >> 4) * 8;
    const int tc = (tid & 15) * 4;
    const uint32_t sA = smem_u32(As);
    const uint32_t sB = smem_u32(Bs);
    const int nit = K / 32;

    for (int t = blockIdx.x; t < ntiles; t += gridDim.x) {
        int tx = t % gx;
        int rem = t / gx;
        int ty = rem % gy;
        int z  = rem / gy;
        const int brow = ty * 128;
        const int bcol = tx * 128;
        const float* Bz = Bm + (size_t)z * bZ;

        unsigned long long acc[4][8];
        #pragma unroll
        for (int i = 0; i < 4; i++)
            #pragma unroll
            for (int j = 0; j < 8; j++) acc[i][j] = 0ull;

        auto load_stage = [&](int st, int k0) {
            #pragma unroll
            for (int j = 0; j < 4; j++) {
                int c = tid + j * 256;
                int kr = c >> 5, sg = c & 31;
                cp16(sA + st * 16384 + kr * 512 + sg * 16,
                     AT + (size_t)(k0 + kr) * ldA + brow + sg * 4);
                cp16(sB + st * 16384 + kr * 512 + sg * 16,
                     Bz + (size_t)(k0 + kr) * ldB + bcol + sg * 4);
            }
        };

        load_stage(0, 0); CP_COMMIT();
        if (nit > 1) { load_stage(1, 32); CP_COMMIT(); }

        for (int it = 0; it < nit; ++it) {
            if (it + 1 < nit) CP_WAIT1(); else CP_WAIT0();
            __syncthreads();
            if (it + 2 < nit) { load_stage((it + 2) % 3, (it + 2) * 32); CP_COMMIT(); }

            const float* Ab = As + (it % 3) * 4096;
            const float* Bb = Bs + (it % 3) * 4096;
            #pragma unroll
            for (int kk = 0; kk < 32; kk++) {
                ulonglong2 av0 = *(const ulonglong2*)(Ab + kk * 128 + tr);
                ulonglong2 av1 = *(const ulonglong2*)(Ab + kk * 128 + tr + 4);
                float4 b0 = *(const float4*)(Bb + kk * 128 + tc);
                float4 b1 = *(const float4*)(Bb + kk * 128 + tc + 64);
                unsigned long long bd[8];
                bd[0] = dup2(b0.x); bd[1] = dup2(b0.y); bd[2] = dup2(b0.z); bd[3] = dup2(b0.w);
                bd[4] = dup2(b1.x); bd[5] = dup2(b1.y); bd[6] = dup2(b1.z); bd[7] = dup2(b1.w);
                unsigned long long ap[4] = { av0.x, av0.y, av1.x, av1.y };
                #pragma unroll
                for (int i = 0; i < 4; i++)
                    #pragma unroll
                    for (int j = 0; j < 8; j++)
                        ffma2(acc[i][j], ap[i], bd[j]);
            }
        }

        const float* biasz = bias + (size_t)z * biasZ;
        const float scale = (EPI == 1) ? d_sigma_inv[z] : 1.f;
        float* Cz = C + (size_t)z * cZ;

        #pragma unroll
        for (int i = 0; i < 4; i++) {
            float vlo[8], vhi[8];
            #pragma unroll
            for (int j = 0; j < 8; j++) upk2(acc[i][j], vlo[j], vhi[j]);
            #pragma unroll
            for (int half = 0; half < 2; half++) {
                int row = brow + tr + 2 * i + half;
                const float* vv = half ? vhi : vlo;
                #pragma unroll
                for (int g = 0; g < 2; g++) {
                    int col = bcol + tc + g * 64;
                    if (EPI != 2) {
                        if (EPI == 4 && col >= Nreal) continue;
                        float4 o;
                        o.x = vv[g*4+0] * scale + biasz[col + 0];
                        o.y = vv[g*4+1] * scale + biasz[col + 1];
                        o.z = vv[g*4+2] * scale + biasz[col + 2];
                        o.w = vv[g*4+3] * scale + biasz[col + 3];
                        *(float4*)(Cz + (size_t)row * ldc + col) = o;
                    } else {
                        #pragma unroll
                        for (int q = 0; q < 4; q++) {
                            int cc = col + q;
                            float v = vv[g*4+q] + biasz[cc];
                            float gt = 1.f / (1.f + expf(-v)) + 0.1f;
                            size_t idx = (size_t)row * ldc + cc;
                            float rr = supr[idx] * gt, ii = supi[idx] * gt;
                            supr[idx] = rr; supi[idx] = ii;
                            magRM[idx] = sqrtf(rr * rr + ii * ii + 1e-8f);
                        }
                    }
                }
            }
        }
        __syncthreads();
    }
}

// ---------------- preprocessing ----------------
__global__ void __launch_bounds__(256)
transpose_k(const float* __restrict__ src, float* __restrict__ dst, int R, int C)
{
    __shared__ float t[32][33];
    int r0 = blockIdx.y * 32, c0 = blockIdx.x * 32;
    int tx = threadIdx.x & 31, ty = threadIdx.x >> 5;
    #pragma unroll
    for (int i = 0; i < 4; i++)
        t[ty + i * 8][tx] = src[(size_t)(r0 + ty + i * 8) * C + c0 + tx];
    __syncthreads();
    #pragma unroll
    for (int i = 0; i < 4; i++)
        dst[(size_t)(c0 + ty + i * 8) * R + r0 + tx] = t[tx][ty + i * 8];
}

__global__ void __launch_bounds__(256)
padW2_k(const float* __restrict__ W2, float* __restrict__ W2p)
{
    int i = blockIdx.x * 256 + threadIdx.x;
    int k = i >> 10, n = i & 1023;
    W2p[i] = (n < NC_) ? W2[(size_t)k * NC_ + n] : 0.f;
}

// LN + gelu, in place (row-major)
__global__ void __launch_bounds__(256)
ln_gelu_k(float* __restrict__ h, const float* __restrict__ g, const float* __restrict__ beta)
{
    const int b = blockIdx.x, tid = threadIdx.x;
    float* row = h + (size_t)b * P_;
    float x[8];
    float sm = 0.f;
    #pragma unroll
    for (int t = 0; t < 8; t++) { x[t] = row[tid + t * 256]; sm += x[t]; }
    float mean = blockReduceSum(sm) * (1.f / (float)P_);
    float vs = 0.f;
    #pragma unroll
    for (int t = 0; t < 8; t++) { float d = x[t] - mean; vs += d * d; }
    float var = blockReduceSum(vs) * (1.f / (float)P_);
    float inv = rsqrtf(var + 1e-5f);
    #pragma unroll
    for (int t = 0; t < 8; t++) {
        int j = tid + t * 256;
        float y = (x[t] - mean) * inv * g[j] + beta[j];
        row[j] = gelu_f(y);
    }
}

// ---------------- spectral normalization ----------------
__global__ void sn_init_k(float* __restrict__ u) {
    int z = blockIdx.y;
    int j = blockIdx.x * 256 + threadIdx.x;
    u[z * P_ + j] = 1.f / sqrtf((float)P_);
}
__global__ void __launch_bounds__(256)
sn_mvWu_f(const float* __restrict__ W, const float* __restrict__ u, float* __restrict__ out,
          int normIn)
{
    int z = blockIdx.y;
    const float* uz = u + z * P_;
    float inv = 1.f;
    {
        float s = 0.f;
        for (int i = threadIdx.x; i < P_; i += 256) { float x = uz[i]; s += x * x; }
        s = blockReduceSum(s);
        if (normIn) inv = 1.f / (sqrtf(s) + 1e-12f);
    }
    const float* Wz = W + (size_t)z * P_ * H2_;
    int warp = threadIdx.x >> 5, lane = threadIdx.x & 31;
    int row = blockIdx.x * 8 + warp;
    const float* wr = Wz + (size_t)row * H2_;
    float s = 0.f;
    for (int k = lane; k < H2_; k += 32) s += wr[k] * (uz[k] * inv);
    #pragma unroll
    for (int o = 16; o; o >>= 1) s += __shfl_xor_sync(0xffffffffu, s, o);
    if (lane == 0) out[z * P_ + row] = s;
}
__global__ void __launch_bounds__(256)
sn_mvWTv_part(const float* __restrict__ W, const float* __restrict__ v, float* __restrict__ part)
{
    __shared__ float vs[256];
    int z = blockIdx.z, rc = blockIdx.y;
    const float* vz = v + z * P_;
    float inv;
    {
        float s = 0.f;
        for (int i = threadIdx.x; i < P_; i += 256) { float x = vz[i]; s += x * x; }
        s = blockReduceSum(s);
        inv = 1.f / (sqrtf(s) + 1e-12f);
    }
    int i0 = rc * 256;
    vs[threadIdx.x] = vz[i0 + threadIdx.x] * inv;
    __syncthreads();
    const float* Wz = W + (size_t)z * P_ * H2_;
    int j = blockIdx.x * 256 + threadIdx.x;
    float s = 0.f;
    #pragma unroll 8
    for (int i = 0; i < 256; i++) s += Wz[(size_t)(i0 + i) * H2_ + j] * vs[i];
    part[(size_t)(z * 8 + rc) * H2_ + j] = s;
}
__global__ void __launch_bounds__(256)
sn_mvWTv_red(const float* __restrict__ part, float* __restrict__ out)
{
    int z = blockIdx.y;
    int j = blockIdx.x * 256 + threadIdx.x;
    float s = 0.f;
    #pragma unroll
    for (int rc = 0; rc < 8; rc++) s += part[(size_t)(z * 8 + rc) * H2_ + j];
    out[z * P_ + j] = s;
}
__global__ void __launch_bounds__(256)
sn_sigma_f(const float* __restrict__ v, const float* __restrict__ t)
{
    int z = blockIdx.x;
    const float* vz = v + z * P_;
    float inv;
    {
        float s = 0.f;
        for (int i = threadIdx.x; i < P_; i += 256) { float x = vz[i]; s += x * x; }
        s = blockReduceSum(s);
        inv = 1.f / (sqrtf(s) + 1e-12f);
    }
    float s = 0.f;
    for (int i = threadIdx.x; i < P_; i += 256) s += (vz[i] * inv) * t[z * P_ + i];
    s = blockReduceSum(s);
    if (threadIdx.x == 0) d_sigma_inv[z] = 1.f / s;
}

// ---------------- fused wave stage (mag row-major) ----------------
__global__ void __launch_bounds__(256)
wave_k(const float* __restrict__ out2,
       const float* __restrict__ gw, const float* __restrict__ betaw,
       const float* __restrict__ phases, const float* __restrict__ temp,
       float* __restrict__ supr, float* __restrict__ supi, float* __restrict__ magRM)
{
    __shared__ float zbuf[H2_];
    __shared__ float wr[NW_][H_];
    __shared__ float wi[NW_][H_];
    __shared__ float mr[H_];
    const int b = blockIdx.x, tid = threadIdx.x;

    for (int s = 0; s < NW_; s++) {
        const float* row = out2 + ((size_t)b * NW_ + s) * H2_;
        float x[8];
        float sm = 0.f;
        #pragma unroll
        for (int t = 0; t < 8; t++) { x[t] = row[tid + t * 256]; sm += x[t]; }
        float mean = blockReduceSum(sm) * (1.f / (float)H2_);
        float vs = 0.f;
        #pragma unroll
        for (int t = 0; t < 8; t++) { float d = x[t] - mean; vs += d * d; }
        float var = blockReduceSum(vs) * (1.f / (float)H2_);
        float inv = rsqrtf(var + 1e-5f);
        float nsq = 0.f;
        #pragma unroll
        for (int t = 0; t < 8; t++) {
            int j = tid + t * 256;
            float y = (x[t] - mean) * inv * gw[s * H2_ + j] + betaw[s * H2_ + j];
            float zz = expf(-y * y);
            zbuf[j] = zz;
            nsq += zz * zz;
        }
        nsq = blockReduceSum(nsq) + 1e-8f;
        float factor = sqrtf(2.25f / nsq);
        float ph = phases[s];
        float c = cosf(ph), sn = sinf(ph);
        #pragma unroll
        for (int t = 0; t < 4; t++) {
            int h = tid + t * 256;
            float a  = zbuf[h] * factor;
            float be = zbuf[h + H_] * factor;
            wr[s][h] = a * c - be * sn;
            wi[s][h] = a * sn + be * c;
        }
        __syncthreads();
    }
    #pragma unroll
    for (int t = 0; t < 4; t++) {
        int h = tid + t * 256;
        mr[h] = (wr[0][h] + wr[1][h] + wr[2][h]) * (1.f / 3.f);
    }
    __syncthreads();
    float mn = 0.f, n0 = 0.f, n1 = 0.f, n2 = 0.f, d0 = 0.f, d1 = 0.f, d2 = 0.f;
    #pragma unroll
    for (int t = 0; t < 4; t++) {
        int h = tid + t * 256;
        float m = mr[h]; mn += m * m;
        float a0 = wr[0][h]; n0 += a0 * a0; d0 += a0 * m;
        float a1 = wr[1][h]; n1 += a1 * a1; d1 += a1 * m;
        float a2 = wr[2][h]; n2 += a2 * a2; d2 += a2 * m;
    }
    mn = blockReduceSum(mn);
    n0 = blockReduceSum(n0); n1 = blockReduceSum(n1); n2 = blockReduceSum(n2);
    d0 = blockReduceSum(d0); d1 = blockReduceSum(d1); d2 = blockReduceSum(d2);

    float mean_norm = sqrtf(mn) + 1e-8f;
    float cs0 = d0 / ((sqrtf(n0) + 1e-8f) * mean_norm);
    float cs1 = d1 / ((sqrtf(n1) + 1e-8f) * mean_norm);
    float cs2 = d2 / ((sqrtf(n2) + 1e-8f) * mean_norm);
    float invT = 1.f / temp[0];
    float l0 = cs0 * invT, l1 = cs1 * invT, l2 = cs2 * invT;
    float mx = fmaxf(l0, fmaxf(l1, l2));
    float e0 = expf(l0 - mx), e1 = expf(l1 - mx), e2 = expf(l2 - mx);
    float es = e0 + e1 + e2;
    float w0 = e0 / es, w1 = e1 / es, w2 = e2 / es;

    #pragma unroll
    for (int t = 0; t < 4; t++) {
        int h = tid + t * 256;
        float r  = wr[0][h] * w0 + wr[1][h] * w1 + wr[2][h] * w2;
        float ii = wi[0][h] * w0 + wi[1][h] * w1 + wi[2][h] * w2;
        size_t idx = (size_t)b * H_ + h;
        supr[idx] = r;
        supi[idx] = ii;
        magRM[idx] = sqrtf(r * r + ii * ii + 1e-8f);
    }
}

// ---------------- top-8 + sparse head fused ----------------
__global__ void __launch_bounds__(256)
topk_head_k(const float* __restrict__ supr, const float* __restrict__ supi,
            const float* __restrict__ W1, const float* __restrict__ b1,
            float* __restrict__ t1)
{
    __shared__ float val[H_];
    __shared__ float s_bv[8];
    __shared__ int   s_bi[8];
    __shared__ int   sel_i[8];
    __shared__ float sel_v[8];
    __shared__ float s_sum;
    const int b = blockIdx.x, tid = threadIdx.x;
    const int lane = tid & 31, wid = tid >> 5;

    #pragma unroll
    for (int t = 0; t < 4; t++) {
        int h = tid + t * 256;
        size_t idx = (size_t)b * H_ + h;
        float r = supr[idx], ii = supi[idx];
        val[h] = r * r + ii * ii;
    }
    if (tid == 0) s_sum = 0.f;
    __syncthreads();

    for (int it = 0; it < 8; it++) {
        float bv = -2.f; int bi = 1 << 30;
        #pragma unroll
        for (int t = 0; t < 4; t++) {
            int h = tid + t * 256;
            float v = val[h];
            if (v > bv) { bv = v; bi = h; }
        }
        #pragma unroll
        for (int o = 16; o; o >>= 1) {
            float ov = __shfl_xor_sync(0xffffffffu, bv, o);
            int   oi = __shfl_xor_sync(0xffffffffu, bi, o);
            if (ov > bv || (ov == bv && oi < bi)) { bv = ov; bi = oi; }
        }
        if (lane == 0) { s_bv[wid] = bv; s_bi[wid] = bi; }
        __syncthreads();
        if (tid == 0) {
            for (int q = 1; q < 8; q++)
                if (s_bv[q] > bv || (s_bv[q] == bv && s_bi[q] < bi)) { bv = s_bv[q]; bi = s_bi[q]; }
            sel_i[it] = bi; sel_v[it] = bv;
            s_sum += bv;
            val[bi] = -1.f;
        }
        __syncthreads();
    }

    float inv = 1.f / (s_sum + 1e-8f);
    int c0 = tid * 4;
    float a0 = b1[c0], a1 = b1[c0 + 1], a2 = b1[c0 + 2], a3 = b1[c0 + 3];
    #pragma unroll
    for (int j = 0; j < 8; j++) {
        float w = sel_v[j] * inv;
        const float* r = W1 + (size_t)sel_i[j] * H_ + c0;
        a0 = fmaf(w, r[0], a0);
        a1 = fmaf(w, r[1], a1);
        a2 = fmaf(w, r[2], a2);
        a3 = fmaf(w, r[3], a3);
    }
    size_t o = (size_t)b * H_ + c0;
    t1[o + 0] = gelu_f(a0);
    t1[o + 1] = gelu_f(a1);
    t1[o + 2] = gelu_f(a2);
    t1[o + 3] = gelu_f(a3);
}

// ---------------- launch ----------------
static inline unsigned pgrid(int ntiles) { return (unsigned)(ntiles < NCTA ? ntiles : NCTA); }

extern "C" void kernel_launch(void* const* d_in, const int* in_sizes, int n_in,
                              void* d_out, int out_size)
{
    const float* x      = (const float*)d_in[0];
    const float* Wp     = (const float*)d_in[1];
    const float* bp     = (const float*)d_in[2];
    const float* gp     = (const float*)d_in[3];
    const float* betap  = (const float*)d_in[4];
    const float* Ww     = (const float*)d_in[5];
    const float* bw     = (const float*)d_in[6];
    const float* gw     = (const float*)d_in[7];
    const float* betaw  = (const float*)d_in[8];
    const float* temp   = (const float*)d_in[9];
    const float* phases = (const float*)d_in[10];
    const float* Wg     = (const float*)d_in[11];
    const float* bg     = (const float*)d_in[12];
    const float* W1     = (const float*)d_in[13];
    const float* b1     = (const float*)d_in[14];
    const float* W2     = (const float*)d_in[15];
    const float* b2     = (const float*)d_in[16];
    float* out = (float*)d_out;

    static cudaStream_t s2 = nullptr;
    static cudaEvent_t evA = nullptr, evB = nullptr;
    if (s2 == nullptr) {
        cudaStreamCreateWithFlags(&s2, cudaStreamNonBlocking);
        cudaEventCreateWithFlags(&evA, cudaEventDisableTiming);
        cudaEventCreateWithFlags(&evB, cudaEventDisableTiming);
        cudaFuncSetAttribute(sgemm<0>, cudaFuncAttributeMaxDynamicSharedMemorySize, SG_SMEM);
        cudaFuncSetAttribute(sgemm<1>, cudaFuncAttributeMaxDynamicSharedMemorySize, SG_SMEM);
        cudaFuncSetAttribute(sgemm<2>, cudaFuncAttributeMaxDynamicSharedMemorySize, SG_SMEM);
        cudaFuncSetAttribute(sgemm<4>, cudaFuncAttributeMaxDynamicSharedMemorySize, SG_SMEM);
    }

    float *pXT, *pH, *pHT, *pOut2, *pSr, *pSi, *pMa, *pMb, *pMaT, *pMbT, *pT1, *pT1T, *pW2p;
    float *pU, *pV, *pT, *pPart;
    cudaGetSymbolAddress((void**)&pXT,   d_xT);
    cudaGetSymbolAddress((void**)&pH,    d_h);
    cudaGetSymbolAddress((void**)&pHT,   d_hT);
    cudaGetSymbolAddress((void**)&pOut2, d_out2);
    cudaGetSymbolAddress((void**)&pSr,   d_supr);
    cudaGetSymbolAddress((void**)&pSi,   d_supi);
    cudaGetSymbolAddress((void**)&pMa,   d_magA);
    cudaGetSymbolAddress((void**)&pMb,   d_magB);
    cudaGetSymbolAddress((void**)&pMaT,  d_magAT);
    cudaGetSymbolAddress((void**)&pMbT,  d_magBT);
    cudaGetSymbolAddress((void**)&pT1,   d_t1);
    cudaGetSymbolAddress((void**)&pT1T,  d_t1T);
    cudaGetSymbolAddress((void**)&pW2p,  d_W2p);
    cudaGetSymbolAddress((void**)&pU,    d_su);
    cudaGetSymbolAddress((void**)&pV,    d_sv);
    cudaGetSymbolAddress((void**)&pT,    d_st);
    cudaGetSymbolAddress((void**)&pPart, d_snp);

    // ---- fork: spectral chain + padW2 on side stream (depends only on Ww / W2) ----
    cudaEventRecord(evA, 0);
    cudaStreamWaitEvent(s2, evA, 0);
    sn_init_k<<<dim3(P_ / 256, NW_), 256, 0, s2>>>(pU);
    for (int it = 0; it < 5; it++) {
        sn_mvWu_f    <<<dim3(P_ / 8, NW_), 256, 0, s2>>>(Ww, pU, pV, it > 0);
        sn_mvWTv_part<<<dim3(H2_ / 256, 8, NW_), 256, 0, s2>>>(Ww, pV, pPart);
        sn_mvWTv_red <<<dim3(H2_ / 256, NW_), 256, 0, s2>>>(pPart, pU);
    }
    sn_mvWu_f<<<dim3(P_ / 8, NW_), 256, 0, s2>>>(Ww, pU, pT, 1);
    sn_sigma_f<<<NW_, 256, 0, s2>>>(pV, pT);
    padW2_k<<<(1024 * 1024) / 256, 256, 0, s2>>>(W2, pW2p);
    cudaEventRecord(evB, s2);

    // ---- main stream: GEMM1 path; GEMM1 uses a FULL grid (one tile per CTA) so the
    // scheduler can dynamically interleave with side-stream work (no static partition).
    transpose_k<<<dim3(IN_ / 32, B_ / 32), 256>>>(x, pXT, B_, IN_);
    sgemm<0><<<1024, 256, SG_SMEM>>>(
        pXT, B_, Wp, P_, 0, bp, 0, pH, P_, 0, IN_,
        nullptr, nullptr, nullptr, 0, 16, 64, 1024);
    ln_gelu_k<<<B_, 256>>>(pH, gp, betap);
    transpose_k<<<dim3(P_ / 32, B_ / 32), 256>>>(pH, pHT, B_, P_);

    // ---- join: wave GEMM needs sigma_inv (and W2p later) ----
    cudaStreamWaitEvent(0, evB, 0);

    // 4) wave GEMM (sigma folded; persistent — runs alone)
    sgemm<1><<<pgrid(3072), 256, SG_SMEM>>>(
        pHT, B_, Ww, H2_, (long long)P_ * H2_, bw, H2_, pOut2, NW_ * H2_, H2_, P_,
        nullptr, nullptr, nullptr, 0, 16, 64, 3072);

    // 5) fused wave stage
    wave_k<<<B_, 256>>>(pOut2, gw, betaw, phases, temp, pSr, pSi, pMa);

    // 6) two gate steps
    transpose_k<<<dim3(H_ / 32, B_ / 32), 256>>>(pMa, pMaT, B_, H_);
    sgemm<2><<<pgrid(512), 256, SG_SMEM>>>(
        pMaT, B_, Wg, H_, 0, bg, 0, nullptr, H_, 0, H_,
        pSr, pSi, pMb, 0, 8, 64, 512);
    transpose_k<<<dim3(H_ / 32, B_ / 32), 256>>>(pMb, pMbT, B_, H_);
    sgemm<2><<<pgrid(512), 256, SG_SMEM>>>(
        pMbT, B_, Wg, H_, 0, bg, 0, nullptr, H_, 0, H_,
        pSr, pSi, pMa, 0, 8, 64, 512);

    // 7) top-8 + sparse head
    topk_head_k<<<B_, 256>>>(pSr, pSi, W1, b1, pT1);
    transpose_k<<<dim3(H_ / 32, B_ / 32), 256>>>(pT1, pT1T, B_, H_);

    // 8) final GEMM
    sgemm<4><<<pgrid(512), 256, SG_SMEM>>>(
        pT1T, B_, pW2p, 1024, 0, b2, 0, out, NC_, 0, H_,
        nullptr, nullptr, nullptr, NC_, 8, 64, 512);
}